// round 16
// baseline (speedup 1.0000x reference)
#include <cuda_runtime.h>

// WKV7 (RWKV-7) recurrence, T=4096, H=32, N=64.
//
// v8: G=8 lanes per row, 4 rows per warp, 512 warps (128 CTAs x 128 thr,
// one CTA per SM). Each lane owns 8 state floats (2x float4). 3-level
// butterflies (x2 interleaved chains: sa_t and y_{t-1}). All per-step
// inputs staged via cp.async smem ring (32 stages, 3 periods ahead).
// Only the a-vector is register-prefetched (it starts the serial chain);
// w,k,b,r,v are loaded at step top and consumed after the butterfly,
// which covers their LDS latency.

#define TT 4096
#define HH 32
#define NN 64
#define CC (HH * NN)       // 2048 channels per timestep

#define SP 8               // steps per sync period
#define NGRP 4             // periods resident in the ring
#define STAGES (SP * NGRP) // 32
#define SFLOATS 384        // 6 vectors x 64 floats per stage

__device__ __forceinline__ void cp16(float* dst_smem, const float* src) {
    unsigned int d = (unsigned int)__cvta_generic_to_shared(dst_smem);
    asm volatile("cp.async.ca.shared.global [%0], [%1], 16;\n"
                 :: "r"(d), "l"(src));
}
__device__ __forceinline__ void cp_commit() {
    asm volatile("cp.async.commit_group;\n");
}
template <int NMAX>
__device__ __forceinline__ void cp_wait() {
    asm volatile("cp.async.wait_group %0;\n" :: "n"(NMAX));
}
__device__ __forceinline__ float dot4(float4 x, float4 y) {
    return fmaf(x.x, y.x, x.y * y.y) + fmaf(x.z, y.z, x.w * y.w);
}

__global__ __launch_bounds__(128) void wkv7_scan_kernel(
    const float* __restrict__ r, const float* __restrict__ w,
    const float* __restrict__ k, const float* __restrict__ v,
    const float* __restrict__ a, const float* __restrict__ b,
    const float* __restrict__ s0, float* __restrict__ out)
{
    __shared__ float stage[STAGES][SFLOATS];  // 48 KB

    const int tid  = threadIdx.x;
    const int cta  = blockIdx.x;          // 0..127
    const int h    = cta >> 2;            // 4 CTAs per head
    const int wid  = tid >> 5;            // 0..3
    const int lane = tid & 31;
    const int grp  = lane >> 3;           // which of the warp's 4 rows
    const int g    = lane & 7;            // lane within the row's 8-lane group
    const int i    = ((cta & 3) << 4) + (wid << 2) + grp;  // row 0..63
    const int j0   = g << 3;              // this lane's 8 j-columns

    // ---- producer setup: threads 0..95 each own one 16B chunk per stage
    //      vector order in a stage: r | w | k | a | b | v   (64 floats each)
    const int pvec  = tid >> 4;           // 0..5 (used when tid<96)
    const int pquad = tid & 15;           // 0..15
    const float* psrc = nullptr;
    if (tid < 96) {
        const float* bases[6] = {r, w, k, a, b, v};
        psrc = bases[pvec] + h * NN + pquad * 4;
    }

    auto issue_period = [&](int tbase) {
        if (tid < 96) {
            #pragma unroll
            for (int u = 0; u < SP; ++u) {
                int t    = tbase + u;
                int tc   = (t < TT) ? t : (TT - 1);
                int slot = t & (STAGES - 1);
                cp16(&stage[slot][pvec * 64 + pquad * 4],
                     psrc + (size_t)tc * CC);
            }
        }
        cp_commit();
    };

    // ---- initial state row chunk (8 floats = 2x float4)
    const float* srow = s0 + ((size_t)(h * NN + i) * NN + j0);
    float4 sa4 = *reinterpret_cast<const float4*>(srow);
    float4 sb4 = *reinterpret_cast<const float4*>(srow + 4);

    const int vibase = h * NN + i;        // v_i / y_i within a [C] vector

    // ---- prologue: fill periods 0,1,2
    issue_period(0 * SP);
    issue_period(1 * SP);
    issue_period(2 * SP);
    cp_wait<1>();
    __syncthreads();

    // ---- prefetch step-0 a-vector (chain head)
    float4 Aa  = *reinterpret_cast<const float4*>(&stage[0][192 + j0]);
    float4 Ab4 = *reinterpret_cast<const float4*>(&stage[0][196 + j0]);

    float q = 0.0f;  // pending y-partial from previous step

    const int NPER = TT / SP;             // 512 sync periods
    for (int hb = 0; hb < NPER; ++hb) {
        __syncthreads();                  // everyone done with period hb-1
        issue_period((hb + 3) * SP);      // refill those stages
        cp_wait<2>();                     // period hb+1 complete
        __syncthreads();                  // visibility

        const int tbase = hb * SP;
        #pragma unroll
        for (int u = 0; u < SP; ++u) {
            const int t  = tbase + u;
            const int sc = t & (STAGES - 1);        // current stage
            const int sn = (t + 1) & (STAGES - 1);  // next stage

            // ---- in-step loads (consumed after the butterfly, ~80 cyc away)
            float4 Ra = *reinterpret_cast<const float4*>(&stage[sc][  0 + j0]);
            float4 Rb = *reinterpret_cast<const float4*>(&stage[sc][  4 + j0]);
            float4 Wa = *reinterpret_cast<const float4*>(&stage[sc][ 64 + j0]);
            float4 Wb = *reinterpret_cast<const float4*>(&stage[sc][ 68 + j0]);
            float4 Ka = *reinterpret_cast<const float4*>(&stage[sc][128 + j0]);
            float4 Kb = *reinterpret_cast<const float4*>(&stage[sc][132 + j0]);
            float4 Ba = *reinterpret_cast<const float4*>(&stage[sc][256 + j0]);
            float4 Bb = *reinterpret_cast<const float4*>(&stage[sc][260 + j0]);
            float  V  = stage[sc][320 + i];

            // ---- sa partial for step t (state BEFORE update)
            float p = dot4(sa4, Aa) + dot4(sb4, Ab4);

            // ---- interleaved 3-level butterflies (width 8):
            //      p (sa_t) and q (y_{t-1}) are independent.
            float ps, qs;
            ps = __shfl_xor_sync(0xffffffffu, p, 4);
            qs = __shfl_xor_sync(0xffffffffu, q, 4);
            p += ps;  q += qs;
            ps = __shfl_xor_sync(0xffffffffu, p, 2);
            qs = __shfl_xor_sync(0xffffffffu, q, 2);
            p += ps;  q += qs;
            ps = __shfl_xor_sync(0xffffffffu, p, 1);
            qs = __shfl_xor_sync(0xffffffffu, q, 1);
            p += ps;  q += qs;

            // ---- emit y for step t-1
            if (g == 0 && t > 0) {
                out[(size_t)(t - 1) * CC + vibase] = q;
            }

            // ---- prefetch a-vector for t+1 (heads next step's chain)
            float4 An  = *reinterpret_cast<const float4*>(&stage[sn][192 + j0]);
            float4 Anb = *reinterpret_cast<const float4*>(&stage[sn][196 + j0]);

            // ---- state update: s = s*w + v_i*k + sa*b
            sa4.x = fmaf(p, Ba.x, fmaf(V, Ka.x, sa4.x * Wa.x));
            sa4.y = fmaf(p, Ba.y, fmaf(V, Ka.y, sa4.y * Wa.y));
            sa4.z = fmaf(p, Ba.z, fmaf(V, Ka.z, sa4.z * Wa.z));
            sa4.w = fmaf(p, Ba.w, fmaf(V, Ka.w, sa4.w * Wa.w));
            sb4.x = fmaf(p, Bb.x, fmaf(V, Kb.x, sb4.x * Wb.x));
            sb4.y = fmaf(p, Bb.y, fmaf(V, Kb.y, sb4.y * Wb.y));
            sb4.z = fmaf(p, Bb.z, fmaf(V, Kb.z, sb4.z * Wb.z));
            sb4.w = fmaf(p, Bb.w, fmaf(V, Kb.w, sb4.w * Wb.w));

            // ---- y partial for step t (reduced during step t+1)
            q = dot4(sa4, Ra) + dot4(sb4, Rb);

            // rotate a-vector prefetch
            Aa = An;  Ab4 = Anb;
        }
    }

    // ---- final y reduction (step T-1)
    q += __shfl_xor_sync(0xffffffffu, q, 4);
    q += __shfl_xor_sync(0xffffffffu, q, 2);
    q += __shfl_xor_sync(0xffffffffu, q, 1);
    if (g == 0) {
        out[(size_t)(TT - 1) * CC + vibase] = q;
    }

    // ---- final state
    float* orow = out + (size_t)TT * CC + ((size_t)(h * NN + i) * NN + j0);
    *reinterpret_cast<float4*>(orow)     = sa4;
    *reinterpret_cast<float4*>(orow + 4) = sb4;
}

// Input order (metadata): seq_length(int32), r, w, k, v, a, b, state2.
// Output: concat(x[T,H,1,N], state2_out[H,N,N]) as float32.
extern "C" void kernel_launch(void* const* d_in, const int* in_sizes, int n_in,
                              void* d_out, int out_size)
{
    const float* r  = (const float*)d_in[1];
    const float* w  = (const float*)d_in[2];
    const float* k  = (const float*)d_in[3];
    const float* v  = (const float*)d_in[4];
    const float* a  = (const float*)d_in[5];
    const float* b  = (const float*)d_in[6];
    const float* s0 = (const float*)d_in[7];
    float* out = (float*)d_out;

    // 128 CTAs x 128 threads = 512 warps (4 rows per warp), 1 CTA/SM
    wkv7_scan_kernel<<<128, 128>>>(r, w, k, v, a, b, s0, out);
}